// round 1
// baseline (speedup 1.0000x reference)
#include <cuda_runtime.h>

typedef unsigned long long ull;

#define B_TILE   16
#define NTHREADS 256
#define T        64
#define D        128
#define WSTRIDE  132        // padded weight row stride in floats (33 float4)
#define WSTRIDE_U 66        // in ull
#define SSTRIDE_U 64        // state row stride in ull (128 floats)

__device__ __forceinline__ ull ffma2(ull a, ull b, ull c) {
    ull r;
    asm("fma.rn.f32x2 %0, %1, %2, %3;" : "=l"(r) : "l"(a), "l"(b), "l"(c));
    return r;
}
__device__ __forceinline__ float sum2(ull a) {
    float lo, hi;
    asm("mov.b64 {%0, %1}, %2;" : "=f"(lo), "=f"(hi) : "l"(a));
    return lo + hi;
}
__device__ __forceinline__ float ex2f(float x) {
    float r; asm("ex2.approx.ftz.f32 %0, %1;" : "=f"(r) : "f"(x)); return r;
}

__global__ void __launch_bounds__(NTHREADS, 2)
fused_hyper_attn(const float* __restrict__ x, const float* __restrict__ state,
                 const float* __restrict__ wk_w, const float* __restrict__ wk_b,
                 const float* __restrict__ wq_w, const float* __restrict__ wq_b,
                 const float* __restrict__ wv_w, const float* __restrict__ wv_b,
                 const float* __restrict__ wo_w, const float* __restrict__ wo_b,
                 const float* __restrict__ V_w,  const float* __restrict__ V_b,
                 float* __restrict__ out)
{
    __shared__ __align__(16) float sm_state[B_TILE * D];     // 8 KB; aliased as s_x later
    __shared__ __align__(16) float sm_w[2 * 32 * WSTRIDE];   // 33 KB: two 32-row tiles
    __shared__ __align__(16) float sm_v[B_TILE * T];         // 4 KB
    __shared__ float sm_s[B_TILE], sm_d[B_TILE], sm_mn[B_TILE], sm_mx[B_TILE];

    const int t  = threadIdx.x;
    const int b0 = blockIdx.x * B_TILE;

    // ---- stage state tile (16 x 128 f32) ----
    {
        const float4* gs = (const float4*)(state + (size_t)b0 * D);
        float4* ss = (float4*)sm_state;
        ss[t]       = gs[t];
        ss[t + 256] = gs[t + 256];
    }

    const ull* st_u = (const ull*)sm_state;
    const ull* wa_u = (const ull*)sm_w;
    const ull* wb_u = (const ull*)(sm_w + 32 * WSTRIDE);
    const int el = t & 15;          // e-lane within 16
    const int bb = t >> 4;          // batch 0..15 (warp w <-> batches {2w,2w+1})
    const ull* srow = st_u + bb * SSTRIDE_U;

    // ---- pass 0: s = sum_e |state.wk_e + bk| * |state.wq_e + bq|
    // ---- pass 1: d = sum_e |state.wv_e + bv| * |state.wo_e + bo|
    for (int pass = 0; pass < 2; pass++) {
        const float* wA = pass == 0 ? wk_w : wv_w;
        const float* wB = pass == 0 ? wq_w : wo_w;
        const float* bA = pass == 0 ? wk_b : wv_b;
        const float* bB = pass == 0 ? wq_b : wo_b;
        float psum = 0.f;
        for (int tile = 0; tile < 4; tile++) {
            __syncthreads();   // previous readers of sm_w done (also orders state stores once)
            {
                const float4* gA = (const float4*)(wA + tile * 32 * D);
                const float4* gB = (const float4*)(wB + tile * 32 * D);
                float4* wa4 = (float4*)sm_w;
                float4* wb4 = (float4*)(sm_w + 32 * WSTRIDE);
                #pragma unroll
                for (int i = 0; i < 4; i++) {
                    int idx = t + i * 256;            // 0..1023 = 32 rows x 32 f4
                    int r = idx >> 5, j = idx & 31;
                    wa4[r * 33 + j] = gA[idx];
                    wb4[r * 33 + j] = gB[idx];
                }
            }
            __syncthreads();
            #pragma unroll
            for (int rep = 0; rep < 2; rep++) {
                int e = el + rep * 16;
                const ull* ra = wa_u + e * WSTRIDE_U;
                const ull* rb = wb_u + e * WSTRIDE_U;
                ull aA0 = 0, aA1 = 0, aB0 = 0, aB1 = 0;
                #pragma unroll 8
                for (int kk = 0; kk < SSTRIDE_U; kk += 2) {
                    ulonglong2 s  = *(const ulonglong2*)(srow + kk);
                    ulonglong2 va = *(const ulonglong2*)(ra + kk);
                    ulonglong2 vb = *(const ulonglong2*)(rb + kk);
                    aA0 = ffma2(s.x, va.x, aA0);
                    aA1 = ffma2(s.y, va.y, aA1);
                    aB0 = ffma2(s.x, vb.x, aB0);
                    aB1 = ffma2(s.y, vb.y, aB1);
                }
                float yA = sum2(aA0) + sum2(aA1) + bA[tile * 32 + e];
                float yB = sum2(aB0) + sum2(aB1) + bB[tile * 32 + e];
                psum += fabsf(yA) * fabsf(yB);
            }
        }
        // reduce over the 16 threads that share batch bb
        #pragma unroll
        for (int off = 8; off > 0; off >>= 1)
            psum += __shfl_xor_sync(0xffffffffu, psum, off, 16);
        if (el == 0) { if (pass == 0) sm_s[bb] = psum; else sm_d[bb] = psum; }
    }

    // ---- V phase: v[b][r] = state[b] . V_w[r] + V_b[r]   (64 rows) ----
    {
        __syncthreads();
        const float4* gV = (const float4*)V_w;
        float4* w4 = (float4*)sm_w;              // 64 rows x 33 f4, contiguous across both halves
        #pragma unroll
        for (int i = 0; i < 8; i++) {
            int idx = t + i * 256;               // 0..2047
            int r = idx >> 5, j = idx & 31;
            w4[r * 33 + j] = gV[idx];
        }
        __syncthreads();
        const int r  = t & 63;
        const int b2 = t >> 6;                   // 0..3
        const ull* rv = (const ull*)sm_w + r * WSTRIDE_U;
        float vb = V_b[r];
        #pragma unroll
        for (int i = 0; i < 4; i++) {
            int b = b2 + i * 4;
            const ull* sr = st_u + b * SSTRIDE_U;
            ull a0 = 0, a1 = 0;
            #pragma unroll 8
            for (int kk = 0; kk < SSTRIDE_U; kk += 2) {
                ulonglong2 s  = *(const ulonglong2*)(sr + kk);
                ulonglong2 vv = *(const ulonglong2*)(rv + kk);
                a0 = ffma2(s.x, vv.x, a0);
                a1 = ffma2(s.y, vv.y, a1);
            }
            sm_v[b * T + r] = sum2(a0) + sum2(a1) + vb;
        }
    }

    // ---- load x over sm_state (state dead now) ----
    __syncthreads();
    float* s_x = sm_state;
    {
        const float4* gx = (const float4*)(x + (size_t)b0 * T);
        ((float4*)s_x)[t] = gx[t];               // 16*64/4 = 256 float4
    }
    __syncthreads();
    if (t < B_TILE) {
        float mn = s_x[t * T], mx = mn;
        #pragma unroll
        for (int k = 1; k < T; k++) {
            float v = s_x[t * T + k];
            mn = fminf(mn, v); mx = fmaxf(mx, v);
        }
        sm_mn[t] = mn; sm_mx[t] = mx;
    }
    __syncthreads();

    // ---- epilogue: per (b,q): softmax over k of c*x_q*x_k (log2 domain), then elu ----
    {
        const int q  = t & 63;
        const int b2 = t >> 6;
        const float inv = 0.08838834764831843f * 1.4426950408889634f;  // log2e / sqrt(128)
        #pragma unroll
        for (int i = 0; i < 4; i++) {
            int b = b2 + i * 4;
            const float* xr = s_x + b * T;
            const float4* xr4 = (const float4*)xr;
            float a2 = xr[q] * (sm_s[b] * inv);
            float m2 = fmaxf(a2 * sm_mx[b], a2 * sm_mn[b]);  // max_k logit (log2 domain)
            float sum = 0.f, ws = 0.f;
            #pragma unroll 4
            for (int j = 0; j < 16; j++) {
                float4 xv = xr4[j];
                float e0 = ex2f(fmaf(a2, xv.x, -m2)); sum += e0; ws = fmaf(e0, xv.x, ws);
                float e1 = ex2f(fmaf(a2, xv.y, -m2)); sum += e1; ws = fmaf(e1, xv.y, ws);
                float e2 = ex2f(fmaf(a2, xv.z, -m2)); sum += e2; ws = fmaf(e2, xv.z, ws);
                float e3 = ex2f(fmaf(a2, xv.w, -m2)); sum += e3; ws = fmaf(e3, xv.w, ws);
            }
            float m = __fdividef(ws, sum);               // m_q = sum p_k x_k
            float r = fmaf(m, sm_d[b], sm_v[b * T + q]); // m*d + v
            out[(size_t)(b0 + b) * T + q] = r > 0.f ? r : expm1f(r);
        }
    }
}

extern "C" void kernel_launch(void* const* d_in, const int* in_sizes, int n_in,
                              void* d_out, int out_size) {
    const float* x     = (const float*)d_in[0];
    const float* state = (const float*)d_in[1];
    const float* wk_w  = (const float*)d_in[2];
    const float* wk_b  = (const float*)d_in[3];
    const float* wq_w  = (const float*)d_in[4];
    const float* wq_b  = (const float*)d_in[5];
    const float* wv_w  = (const float*)d_in[6];
    const float* wv_b  = (const float*)d_in[7];
    const float* wo_w  = (const float*)d_in[8];
    const float* wo_b  = (const float*)d_in[9];
    const float* V_w   = (const float*)d_in[10];
    const float* V_b   = (const float*)d_in[11];

    int nb   = in_sizes[0] / T;        // 4096 batches
    int grid = nb / B_TILE;            // 256 blocks
    fused_hyper_attn<<<grid, NTHREADS>>>(x, state,
                                         wk_w, wk_b, wq_w, wq_b,
                                         wv_w, wv_b, wo_w, wo_b,
                                         V_w, V_b, (float*)d_out);
}

// round 2
// speedup vs baseline: 1.3706x; 1.3706x over previous
#include <cuda_runtime.h>

typedef unsigned long long ull;

#define B_TILE   16
#define NTHREADS 256
#define T        64
#define D        128

__device__ __forceinline__ ull ffma2(ull a, ull b, ull c) {
    ull r;
    asm("fma.rn.f32x2 %0, %1, %2, %3;" : "=l"(r) : "l"(a), "l"(b), "l"(c));
    return r;
}
__device__ __forceinline__ float sum2(ull a) {
    float lo, hi;
    asm("mov.b64 {%0, %1}, %2;" : "=f"(lo), "=f"(hi) : "l"(a));
    return lo + hi;
}
__device__ __forceinline__ float ex2f(float x) {
    float r; asm("ex2.approx.ftz.f32 %0, %1;" : "=f"(r) : "f"(x)); return r;
}

__global__ void __launch_bounds__(NTHREADS, 2)
fused_hyper_attn(const float* __restrict__ x, const float* __restrict__ state,
                 const float* __restrict__ wk_w, const float* __restrict__ wk_b,
                 const float* __restrict__ wq_w, const float* __restrict__ wq_b,
                 const float* __restrict__ wv_w, const float* __restrict__ wv_b,
                 const float* __restrict__ wo_w, const float* __restrict__ wo_b,
                 const float* __restrict__ V_w,  const float* __restrict__ V_b,
                 float* __restrict__ out)
{
    __shared__ __align__(16) float sm_state[B_TILE * D];   // 8 KB
    __shared__ __align__(16) float sm_x[B_TILE * T];       // 4 KB
    __shared__ __align__(16) float sm_v[B_TILE * T];       // 4 KB
    __shared__ float sm_s[B_TILE], sm_d[B_TILE], sm_mn[B_TILE], sm_mx[B_TILE];

    const int t  = threadIdx.x;
    const int b0 = blockIdx.x * B_TILE;

    // ---- stage state (16x128) and x (16x64) ----
    {
        const float4* gs = (const float4*)(state + (size_t)b0 * D);
        ((float4*)sm_state)[t]       = gs[t];
        ((float4*)sm_state)[t + 256] = gs[t + 256];
        ((float4*)sm_x)[t] = ((const float4*)(x + (size_t)b0 * T))[t];
    }
    if (t < B_TILE) { sm_s[t] = 0.f; sm_d[t] = 0.f; }
    __syncthreads();

    // ---- per-batch min/max of x (warp 0's first 16 lanes, overlapped) ----
    if (t < B_TILE) {
        float mn = sm_x[t * T], mx = mn;
        #pragma unroll
        for (int k = 1; k < T; k++) {
            float v = sm_x[t * T + k];
            mn = fminf(mn, v); mx = fmaxf(mx, v);
        }
        sm_mn[t] = mn; sm_mx[t] = mx;
    }

    // ---- main GEMVs: threads 0-127 -> (K,Q) pair, threads 128-255 -> (V,O) pair.
    // Thread owns row e of both matrices, accumulates over all 16 batches.
    // Weights read ONCE per block straight from L2 (LDG.128); state via
    // uniform-broadcast LDS.128.
    {
        const int grp = t >> 7;         // 0: K/Q  1: V/O
        const int e   = t & 127;
        const float* wAp = grp ? wv_w : wk_w;
        const float* wBp = grp ? wo_w : wq_w;
        const float  bAv = (grp ? wv_b : wk_b)[e];
        const float  bBv = (grp ? wo_b : wq_b)[e];
        const ulonglong2* wa = (const ulonglong2*)(wAp + (size_t)e * D);
        const ulonglong2* wb = (const ulonglong2*)(wBp + (size_t)e * D);
        const ulonglong2* st = (const ulonglong2*)sm_state;   // [16][32]

        ull accA[B_TILE], accB[B_TILE];
        #pragma unroll
        for (int b = 0; b < B_TILE; b++) { accA[b] = 0ull; accB[b] = 0ull; }

        #pragma unroll 8
        for (int j = 0; j < 32; j++) {
            ulonglong2 va = wa[j];
            ulonglong2 vb = wb[j];
            #pragma unroll
            for (int b = 0; b < B_TILE; b++) {
                ulonglong2 s = st[b * 32 + j];
                accA[b] = ffma2(s.x, va.x, accA[b]);
                accA[b] = ffma2(s.y, va.y, accA[b]);
                accB[b] = ffma2(s.x, vb.x, accB[b]);
                accB[b] = ffma2(s.y, vb.y, accB[b]);
            }
        }

        float p[B_TILE];
        #pragma unroll
        for (int b = 0; b < B_TILE; b++)
            p[b] = fabsf(sum2(accA[b]) + bAv) * fabsf(sum2(accB[b]) + bBv);

        // warp-reduce each p[b] over the 32 e-lanes
        #pragma unroll
        for (int b = 0; b < B_TILE; b++) {
            #pragma unroll
            for (int off = 16; off > 0; off >>= 1)
                p[b] += __shfl_xor_sync(0xffffffffu, p[b], off);
        }
        if ((t & 31) == 0) {
            float* dst = grp ? sm_d : sm_s;
            #pragma unroll
            for (int b = 0; b < B_TILE; b++) atomicAdd(&dst[b], p[b]);
        }
    }

    // ---- V phase: v[b][r] = state[b] . V_w[r] + V_b[r], 64 rows, 4 batches/thread
    {
        const int r  = t & 63;
        const int bg = t >> 6;                 // 0..3, uniform per warp
        const ulonglong2* wv2 = (const ulonglong2*)(V_w + (size_t)r * D);
        const ulonglong2* st  = (const ulonglong2*)sm_state;
        const float vbias = V_b[r];
        ull acc[4];
        #pragma unroll
        for (int i = 0; i < 4; i++) acc[i] = 0ull;
        #pragma unroll 8
        for (int j = 0; j < 32; j++) {
            ulonglong2 v = wv2[j];
            #pragma unroll
            for (int i = 0; i < 4; i++) {
                ulonglong2 s = st[(bg * 4 + i) * 32 + j];
                acc[i] = ffma2(s.x, v.x, acc[i]);
                acc[i] = ffma2(s.y, v.y, acc[i]);
            }
        }
        #pragma unroll
        for (int i = 0; i < 4; i++)
            sm_v[(bg * 4 + i) * T + r] = sum2(acc[i]) + vbias;
    }

    __syncthreads();

    // ---- epilogue: per (b,q) softmax over k of c*x_q*x_k (log2 domain), then elu
    {
        const int q  = t & 63;
        const int b2 = t >> 6;
        const float inv = 0.08838834764831843f * 1.4426950408889634f;  // log2e/sqrt(128)
        #pragma unroll
        for (int i = 0; i < 4; i++) {
            int b = b2 + i * 4;
            const float* xr = sm_x + b * T;
            const float4* xr4 = (const float4*)xr;
            float a2 = xr[q] * (sm_s[b] * inv);
            float m2 = fmaxf(a2 * sm_mx[b], a2 * sm_mn[b]);
            float sum = 0.f, ws = 0.f;
            #pragma unroll 4
            for (int j = 0; j < 16; j++) {
                float4 xv = xr4[j];
                float e0 = ex2f(fmaf(a2, xv.x, -m2)); sum += e0; ws = fmaf(e0, xv.x, ws);
                float e1 = ex2f(fmaf(a2, xv.y, -m2)); sum += e1; ws = fmaf(e1, xv.y, ws);
                float e2 = ex2f(fmaf(a2, xv.z, -m2)); sum += e2; ws = fmaf(e2, xv.z, ws);
                float e3 = ex2f(fmaf(a2, xv.w, -m2)); sum += e3; ws = fmaf(e3, xv.w, ws);
            }
            float m = __fdividef(ws, sum);
            float r = fmaf(m, sm_d[b], sm_v[b * T + q]);
            out[(size_t)(b0 + b) * T + q] = r > 0.f ? r : expm1f(r);
        }
    }
}

extern "C" void kernel_launch(void* const* d_in, const int* in_sizes, int n_in,
                              void* d_out, int out_size) {
    const float* x     = (const float*)d_in[0];
    const float* state = (const float*)d_in[1];
    const float* wk_w  = (const float*)d_in[2];
    const float* wk_b  = (const float*)d_in[3];
    const float* wq_w  = (const float*)d_in[4];
    const float* wq_b  = (const float*)d_in[5];
    const float* wv_w  = (const float*)d_in[6];
    const float* wv_b  = (const float*)d_in[7];
    const float* wo_w  = (const float*)d_in[8];
    const float* wo_b  = (const float*)d_in[9];
    const float* V_w   = (const float*)d_in[10];
    const float* V_b   = (const float*)d_in[11];

    int nb   = in_sizes[0] / T;        // 4096 batches
    int grid = nb / B_TILE;            // 256 blocks
    fused_hyper_attn<<<grid, NTHREADS>>>(x, state,
                                         wk_w, wk_b, wq_w, wq_b,
                                         wv_w, wv_b, wo_w, wo_b,
                                         V_w, V_b, (float*)d_out);
}

// round 4
// speedup vs baseline: 1.7004x; 1.2407x over previous
#include <cuda_runtime.h>
#include <cstdint>

typedef unsigned long long ull;

#define B_TILE   16
#define NTHREADS 256
#define T        64
#define D        128
#define CTILE    16          // columns per weight tile (floats)
#define NTILES   8           // 128 / 16
#define RSTRIDE  20          // padded tile row stride in floats (5 float4, conflict-free)
#define NROWS    576         // wk(128)+wq(128)+wv(128)+wo(128)+V(64)
#define TILE_F   (NROWS * RSTRIDE)   // 11520 floats per buffer

// dynamic smem layout (float offsets)
#define OFF_WS    0
#define OFF_STATE (2 * TILE_F)            // 23040
#define OFF_X     (OFF_STATE + B_TILE*D)  // 25088
#define OFF_V     (OFF_X + B_TILE*T)      // 26112
#define OFF_S     (OFF_V + B_TILE*T)      // 27136
#define OFF_D     (OFF_S + B_TILE)
#define OFF_MN    (OFF_D + B_TILE)
#define OFF_MX    (OFF_MN + B_TILE)
#define SMEM_F    (OFF_MX + B_TILE)       // 27200 floats = 108800 B

__device__ __forceinline__ ull ffma2(ull a, ull b, ull c) {
    ull r;
    asm("fma.rn.f32x2 %0, %1, %2, %3;" : "=l"(r) : "l"(a), "l"(b), "l"(c));
    return r;
}
__device__ __forceinline__ float sum2(ull a) {
    float lo, hi;
    asm("mov.b64 {%0, %1}, %2;" : "=f"(lo), "=f"(hi) : "l"(a));
    return lo + hi;
}
__device__ __forceinline__ float ex2f(float x) {
    float r; asm("ex2.approx.ftz.f32 %0, %1;" : "=f"(r) : "f"(x)); return r;
}
__device__ __forceinline__ void cp16(unsigned int dst, const void* src) {
    asm volatile("cp.async.ca.shared.global [%0], [%1], 16;" :: "r"(dst), "l"(src));
}
__device__ __forceinline__ void cp_commit() {
    asm volatile("cp.async.commit_group;" ::: "memory");
}
template<int N> __device__ __forceinline__ void cp_wait() {
    asm volatile("cp.async.wait_group %0;" :: "n"(N) : "memory");
}

__global__ void __launch_bounds__(NTHREADS, 2)
fused_hyper_attn(const float* __restrict__ x, const float* __restrict__ state,
                 const float* __restrict__ wk_w, const float* __restrict__ wk_b,
                 const float* __restrict__ wq_w, const float* __restrict__ wq_b,
                 const float* __restrict__ wv_w, const float* __restrict__ wv_b,
                 const float* __restrict__ wo_w, const float* __restrict__ wo_b,
                 const float* __restrict__ V_w,  const float* __restrict__ V_b,
                 float* __restrict__ out)
{
    extern __shared__ __align__(16) float sm[];
    const int t  = threadIdx.x;
    const int b0 = blockIdx.x * B_TILE;
    const unsigned int sm_u32 = (unsigned int)__cvta_generic_to_shared(sm);

    // ---- stage state (16x128) and x (16x64), init reductions ----
    {
        const float4* gs = (const float4*)(state + (size_t)b0 * D);
        ((float4*)(sm + OFF_STATE))[t]       = gs[t];
        ((float4*)(sm + OFF_STATE))[t + 256] = gs[t + 256];
        ((float4*)(sm + OFF_X))[t] = ((const float4*)(x + (size_t)b0 * T))[t];
    }
    if (t < B_TILE) { sm[OFF_S + t] = 0.f; sm[OFF_D + t] = 0.f; }

    // ---- stage weight tiles (cp.async, double buffered) ----
    #define STAGE(TI)                                                          \
    do {                                                                       \
        const int c0_ = (TI) * CTILE;                                          \
        const unsigned int wb_ = sm_u32 + (OFF_WS + ((TI) & 1) * TILE_F) * 4;  \
        _Pragma("unroll")                                                      \
        for (int i_ = 0; i_ < 9; i_++) {                                       \
            int q_ = t + i_ * 256;                                             \
            int row_ = q_ >> 2, cq_ = q_ & 3;                                  \
            const float* src_;                                                 \
            if      (i_ < 2) src_ = wk_w + (size_t)row_ * D;                   \
            else if (i_ < 4) src_ = wq_w + (size_t)(row_ - 128) * D;           \
            else if (i_ < 6) src_ = wv_w + (size_t)(row_ - 256) * D;           \
            else if (i_ < 8) src_ = wo_w + (size_t)(row_ - 384) * D;           \
            else             src_ = V_w  + (size_t)(row_ - 512) * D;           \
            cp16(wb_ + (unsigned int)(row_ * RSTRIDE + cq_ * 4) * 4,           \
                 src_ + c0_ + cq_ * 4);                                        \
        }                                                                      \
        cp_commit();                                                           \
    } while (0)

    STAGE(0);
    STAGE(1);

    __syncthreads();   // state/x visible (cheap; also orders s/d init)

    // ---- per-batch min/max of x (16 threads, overlapped) ----
    if (t < B_TILE) {
        const float* xr = sm + OFF_X + t * T;
        float mn = xr[0], mx = mn;
        #pragma unroll
        for (int k = 1; k < T; k++) {
            float v = xr[k];
            mn = fminf(mn, v); mx = fmaxf(mx, v);
        }
        sm[OFF_MN + t] = mn; sm[OFF_MX + t] = mx;
    }

    // ---- row ownership ----
    const int g    = t >> 7;          // 0: K/Q   1: V/O
    const int e    = t & 127;
    const int rowA = g * 256 + e;          // wk or wv
    const int rowB = g * 256 + 128 + e;    // wq or wo
    const int rV   = t & 63;               // V_w row
    const int rowV = 512 + rV;
    const int bg   = t >> 6;               // 0..3 (uniform per warp)
    const float bAv = (g ? wv_b : wk_b)[e];
    const float bBv = (g ? wo_b : wq_b)[e];
    const float vBv = V_b[rV];

    ull accA[B_TILE], accB[B_TILE], accV[4];
    #pragma unroll
    for (int b = 0; b < B_TILE; b++) { accA[b] = 0ull; accB[b] = 0ull; }
    #pragma unroll
    for (int i = 0; i < 4; i++) accV[i] = 0ull;

    const ulonglong2* st = (const ulonglong2*)(sm + OFF_STATE);  // [16][32] 16B units

    // ---- pipelined main loop over 8 column tiles ----
    for (int ti = 0; ti < NTILES; ti++) {
        if (ti < NTILES - 1) cp_wait<1>(); else cp_wait<0>();
        __syncthreads();                       // tile ti visible to all

        const ulonglong2* wt = (const ulonglong2*)(sm + OFF_WS + (ti & 1) * TILE_F);
        const int jb = ti * 4;                 // float4-column base within state row
        #pragma unroll
        for (int j = 0; j < 4; j++) {
            ulonglong2 va = wt[rowA * 5 + j];
            ulonglong2 vb = wt[rowB * 5 + j];
            ulonglong2 vv = wt[rowV * 5 + j];
            #pragma unroll
            for (int b = 0; b < B_TILE; b++) {
                ulonglong2 s = st[b * 32 + jb + j];
                accA[b] = ffma2(s.x, va.x, accA[b]);
                accA[b] = ffma2(s.y, va.y, accA[b]);
                accB[b] = ffma2(s.x, vb.x, accB[b]);
                accB[b] = ffma2(s.y, vb.y, accB[b]);
            }
            #pragma unroll
            for (int i = 0; i < 4; i++) {
                ulonglong2 s = st[(bg * 4 + i) * 32 + jb + j];
                accV[i] = ffma2(s.x, vv.x, accV[i]);
                accV[i] = ffma2(s.y, vv.y, accV[i]);
            }
        }

        __syncthreads();                       // all done reading buf[ti&1]
        if (ti + 2 < NTILES) STAGE(ti + 2);
    }

    // ---- finalize s[b] / d[b]: p = |yA|*|yB|, warp-reduce, atomic into smem ----
    {
        float p[B_TILE];
        #pragma unroll
        for (int b = 0; b < B_TILE; b++)
            p[b] = fabsf(sum2(accA[b]) + bAv) * fabsf(sum2(accB[b]) + bBv);
        #pragma unroll
        for (int b = 0; b < B_TILE; b++) {
            #pragma unroll
            for (int off = 16; off > 0; off >>= 1)
                p[b] += __shfl_xor_sync(0xffffffffu, p[b], off);
        }
        if ((t & 31) == 0) {
            float* dst = sm + (g ? OFF_D : OFF_S);
            #pragma unroll
            for (int b = 0; b < B_TILE; b++) atomicAdd(&dst[b], p[b]);
        }
    }

    // ---- finalize v[b][r] ----
    #pragma unroll
    for (int i = 0; i < 4; i++)
        sm[OFF_V + (bg * 4 + i) * T + rV] = sum2(accV[i]) + vBv;

    __syncthreads();

    // ---- epilogue: per (b,q) softmax over k of c*x_q*x_k (log2 domain), then elu
    {
        const int q  = t & 63;
        const int b2 = t >> 6;
        const float inv = 0.08838834764831843f * 1.4426950408889634f;  // log2e/sqrt(128)
        #pragma unroll
        for (int i = 0; i < 4; i++) {
            int b = b2 + i * 4;
            const float* xr = sm + OFF_X + b * T;
            const float4* xr4 = (const float4*)xr;
            float a2 = xr[q] * (sm[OFF_S + b] * inv);
            float m2 = fmaxf(a2 * sm[OFF_MX + b], a2 * sm[OFF_MN + b]);
            float sum = 0.f, ws = 0.f;
            #pragma unroll 4
            for (int j = 0; j < 16; j++) {
                float4 xv = xr4[j];
                float e0 = ex2f(fmaf(a2, xv.x, -m2)); sum += e0; ws = fmaf(e0, xv.x, ws);
                float e1 = ex2f(fmaf(a2, xv.y, -m2)); sum += e1; ws = fmaf(e1, xv.y, ws);
                float e2 = ex2f(fmaf(a2, xv.z, -m2)); sum += e2; ws = fmaf(e2, xv.z, ws);
                float e3 = ex2f(fmaf(a2, xv.w, -m2)); sum += e3; ws = fmaf(e3, xv.w, ws);
            }
            float m = __fdividef(ws, sum);
            float r = fmaf(m, sm[OFF_D + b], sm[OFF_V + b * T + q]);
            out[(size_t)(b0 + b) * T + q] = r > 0.f ? r : expm1f(r);
        }
    }
}

extern "C" void kernel_launch(void* const* d_in, const int* in_sizes, int n_in,
                              void* d_out, int out_size) {
    const float* x     = (const float*)d_in[0];
    const float* state = (const float*)d_in[1];
    const float* wk_w  = (const float*)d_in[2];
    const float* wk_b  = (const float*)d_in[3];
    const float* wq_w  = (const float*)d_in[4];
    const float* wq_b  = (const float*)d_in[5];
    const float* wv_w  = (const float*)d_in[6];
    const float* wv_b  = (const float*)d_in[7];
    const float* wo_w  = (const float*)d_in[8];
    const float* wo_b  = (const float*)d_in[9];
    const float* V_w   = (const float*)d_in[10];
    const float* V_b   = (const float*)d_in[11];

    static int configured = 0;
    if (!configured) {
        cudaFuncSetAttribute(fused_hyper_attn,
                             cudaFuncAttributeMaxDynamicSharedMemorySize,
                             SMEM_F * 4);
        configured = 1;
    }

    int nb   = in_sizes[0] / T;        // 4096 batches
    int grid = nb / B_TILE;            // 256 blocks
    fused_hyper_attn<<<grid, NTHREADS, SMEM_F * 4>>>(x, state,
                                                     wk_w, wk_b, wq_w, wq_b,
                                                     wv_w, wv_b, wo_w, wo_b,
                                                     V_w, V_b, (float*)d_out);
}